// round 8
// baseline (speedup 1.0000x reference)
#include <cuda_runtime.h>
#include <cuda_bf16.h>
#include <cstdint>

static constexpr int T_TOK = 8192;
static constexpr int C_DIM = 2048;
static constexpr int K3 = 3 * C_DIM;       // 6144
static constexpr int BM = 128;
static constexpr int BN = 256;
static constexpr int BK = 128;             // bf16 per K-chunk (256B rows)
static constexpr int NKCH = K3 / BK;       // 48
static constexpr int ROW_BYTES = 272;      // 256B data + 16B pad (conflict-free ldmatrix)
static constexpr int AROWS = BM;
static constexpr int STAGE_ROWS = BM + BN; // 384
static constexpr int STAGE_BYTES = STAGE_ROWS * ROW_BYTES;  // 104448
static constexpr int STAGES = 2;
static constexpr int GEMM_SMEM = STAGES * STAGE_BYTES;      // 208896
static constexpr int GTHREADS = 512;       // 16 warps: 2 over M x 8 over N

// -------- scratch (static __device__; no allocation allowed) --------
__device__ __nv_bfloat16 g_xs [(size_t)T_TOK * K3];
__device__ __nv_bfloat16 g_ys [(size_t)T_TOK * K3];
__device__ __nv_bfloat16 g_aos[(size_t)T_TOK * K3];
__device__ __nv_bfloat16 g_wq [(size_t)C_DIM * K3];
__device__ __nv_bfloat16 g_wkv[(size_t)(2 * C_DIM) * K3];
__device__ __nv_bfloat16 g_wo [(size_t)C_DIM * K3];
__device__ float g_q  [(size_t)T_TOK * C_DIM];
__device__ float g_kv [(size_t)T_TOK * 2 * C_DIM];
__device__ float g_bkv[2 * C_DIM];

// -------- PTX helpers (sm_80+ only; no 'a'-suffix features) --------
__device__ __forceinline__ uint32_t smem_u32(const void* p) {
    uint32_t a;
    asm("{ .reg .u64 t; cvta.to.shared.u64 t, %1; cvt.u32.u64 %0, t; }" : "=r"(a) : "l"(p));
    return a;
}
#define CP_ASYNC16(s, g) \
    asm volatile("cp.async.cg.shared.global [%0], [%1], 16;" :: "r"((uint32_t)(s)), "l"(g) : "memory")
#define CP_COMMIT() asm volatile("cp.async.commit_group;" ::: "memory")

#define LDSM4(r, addr) \
    asm volatile("ldmatrix.sync.aligned.m8n8.x4.shared.b16 {%0,%1,%2,%3}, [%4];" \
        : "=r"((r)[0]), "=r"((r)[1]), "=r"((r)[2]), "=r"((r)[3]) : "r"(addr))

#define MMA16816(d, a, b0, b1) \
    asm volatile("mma.sync.aligned.m16n8k16.row.col.f32.bf16.bf16.f32 " \
        "{%0,%1,%2,%3}, {%4,%5,%6,%7}, {%8,%9}, {%0,%1,%2,%3};" \
        : "+f"((d)[0]), "+f"((d)[1]), "+f"((d)[2]), "+f"((d)[3]) \
        : "r"((a)[0]), "r"((a)[1]), "r"((a)[2]), "r"((a)[3]), "r"(b0), "r"(b1))

__device__ __forceinline__ uint32_t pack_bf16x2(float x, float y) {
    __nv_bfloat162 h = __floats2bfloat162_rn(x, y);
    return *(uint32_t*)&h;
}

// -------- fused split conversions --------
__global__ void split_acts_kernel(const float* __restrict__ x, const float* __restrict__ y,
                                  __nv_bfloat16* __restrict__ xs, __nv_bfloat16* __restrict__ ys) {
    const float* src = blockIdx.y ? y : x;
    __nv_bfloat16* dst = blockIdx.y ? ys : xs;
    size_t i = (size_t)blockIdx.x * blockDim.x + threadIdx.x;
    int r = (int)(i >> 11);
    int c = (int)(i & (C_DIM - 1));
    float v = src[i];
    __nv_bfloat16 hi = __float2bfloat16_rn(v);
    __nv_bfloat16 lo = __float2bfloat16_rn(v - __bfloat162float(hi));
    size_t o = (size_t)r * K3 + c;
    dst[o] = hi; dst[o + C_DIM] = hi; dst[o + 2 * C_DIM] = lo;
}
__global__ void split_wgts_kernel(const float* __restrict__ Wq, const float* __restrict__ Wk,
                                  const float* __restrict__ Wv, const float* __restrict__ Wo,
                                  __nv_bfloat16* __restrict__ wq, __nv_bfloat16* __restrict__ wkv,
                                  __nv_bfloat16* __restrict__ wo) {
    int sel = blockIdx.y;
    const float* src = (sel == 0) ? Wq : (sel == 1) ? Wk : (sel == 2) ? Wv : Wo;
    __nv_bfloat16* dst = (sel == 0) ? wq : (sel == 1) ? wkv
                       : (sel == 2) ? wkv + (size_t)C_DIM * K3 : wo;
    size_t i = (size_t)blockIdx.x * blockDim.x + threadIdx.x;
    int r = (int)(i >> 11);
    int c = (int)(i & (C_DIM - 1));
    float v = src[i];
    __nv_bfloat16 hi = __float2bfloat16_rn(v);
    __nv_bfloat16 lo = __float2bfloat16_rn(v - __bfloat162float(hi));
    size_t o = (size_t)r * K3 + c;
    dst[o] = hi; dst[o + C_DIM] = lo; dst[o + 2 * C_DIM] = hi;
}
__global__ void concat_bias_kernel(const float* __restrict__ bk,
                                   const float* __restrict__ bv,
                                   float* __restrict__ dst) {
    int i = blockIdx.x * blockDim.x + threadIdx.x;
    dst[i] = (i < C_DIM) ? bk[i] : bv[i - C_DIM];
}

// -------- HMMA GEMM core (512 threads): C = A[M,K3] @ B[N,K3]^T + bias (+res) --------
// 96KB per stage = 6144 x 16B chunks = 12 iters of 512 threads.
// parts 0..7 (one per ks step): parts 0-3 carry 2 iters, parts 4-7 carry 1.
__device__ __forceinline__ void load_tiles_part(const __nv_bfloat16* __restrict__ A,
                                                const __nv_bfloat16* __restrict__ B,
                                                int rowA0, int rowB0, int k0,
                                                uint32_t sbase, int tid, int part) {
    int first = (part < 4) ? 2 * part : part + 4;
    int count = (part < 4) ? 2 : 1;
#pragma unroll
    for (int i = first; i < first + 2; i++) {
        if (i >= first + count) break;
        int idx = i * GTHREADS + tid;
        int row = idx >> 4;            // 16 x 16B chunks per 256B row
        int c = idx & 15;
        const __nv_bfloat16* g = (row < AROWS)
            ? A + (size_t)(rowA0 + row) * K3 + (k0 + c * 8)
            : B + (size_t)(rowB0 + row - AROWS) * K3 + (k0 + c * 8);
        CP_ASYNC16(sbase + row * ROW_BYTES + c * 16, g);
    }
}
__device__ __forceinline__ void load_tiles(const __nv_bfloat16* __restrict__ A,
                                           const __nv_bfloat16* __restrict__ B,
                                           int rowA0, int rowB0, int k0,
                                           uint32_t sbase, int tid) {
#pragma unroll
    for (int p = 0; p < 8; p++)
        load_tiles_part(A, B, rowA0, rowB0, k0, sbase, tid, p);
}

__device__ __forceinline__ void gemm_core(const __nv_bfloat16* __restrict__ A,
                                          const __nv_bfloat16* __restrict__ B,
                                          const float* __restrict__ bias,
                                          const float* __restrict__ residual,
                                          float* __restrict__ Cout, int ldc,
                                          int rowA0, int rowB0, char* smem) {
    uint32_t sb = smem_u32(smem);
    int tid = threadIdx.x;
    int wid = tid >> 5, lid = tid & 31;
    int warp_m = wid & 1;                   // 2 warps over M (64 rows each)
    int warp_n = wid >> 1;                  // 8 warps over N (32 cols each)

    float acc[4][4][4];
#pragma unroll
    for (int mi = 0; mi < 4; mi++)
#pragma unroll
        for (int ni = 0; ni < 4; ni++)
#pragma unroll
            for (int e = 0; e < 4; e++) acc[mi][ni][e] = 0.f;

    // prologue: fill stage 0
    load_tiles(A, B, rowA0, rowB0, 0, sb, tid);
    CP_COMMIT();

    uint32_t a_base = sb + (warp_m * 64 + (lid & 15)) * ROW_BYTES + ((lid >> 4) << 4);
    int g = lid >> 3;
    uint32_t b_base = sb + (AROWS + warp_n * 32 + ((g >> 1) << 3) + (lid & 7)) * ROW_BYTES
                         + ((g & 1) << 4);

    for (int k = 0; k < NKCH; k++) {
        asm volatile("cp.async.wait_group 0;" ::: "memory");
        __syncthreads();

        uint32_t sa  = a_base + (k & 1) * STAGE_BYTES;
        uint32_t sbb = b_base + (k & 1) * STAGE_BYTES;

        int pk = k + 1;
        bool do_pf = (pk < NKCH);
        uint32_t pf_base = sb + (pk & 1) * STAGE_BYTES;
        int pf_k0 = pk * BK;

#pragma unroll
        for (int ks = 0; ks < 8; ks++) {    // 8 x k16 per BK=128
            uint32_t afr[4][4], bfr[2][4];
#pragma unroll
            for (int mi = 0; mi < 4; mi++)
                LDSM4(afr[mi], sa + mi * 16 * ROW_BYTES + ks * 32);
#pragma unroll
            for (int ni2 = 0; ni2 < 2; ni2++)
                LDSM4(bfr[ni2], sbb + ni2 * 16 * ROW_BYTES + ks * 32);
            // spread + front-loaded prefetch of next chunk
            if (do_pf) {
                load_tiles_part(A, B, rowA0, rowB0, pf_k0, pf_base, tid, ks);
                if (ks == 7) CP_COMMIT();
            }
#pragma unroll
            for (int mi = 0; mi < 4; mi++)
#pragma unroll
                for (int ni2 = 0; ni2 < 2; ni2++) {
                    MMA16816(acc[mi][2 * ni2],     afr[mi], bfr[ni2][0], bfr[ni2][1]);
                    MMA16816(acc[mi][2 * ni2 + 1], afr[mi], bfr[ni2][2], bfr[ni2][3]);
                }
        }
    }

    int qrow = lid >> 2, qcol = (lid & 3) * 2;
#pragma unroll
    for (int mi = 0; mi < 4; mi++) {
#pragma unroll
        for (int ni = 0; ni < 4; ni++) {
            int r0 = rowA0 + warp_m * 64 + mi * 16 + qrow;
            int col = rowB0 + warp_n * 32 + ni * 8 + qcol;
            float2 bb = *(const float2*)(bias + col);
            float2 v0 = make_float2(acc[mi][ni][0] + bb.x, acc[mi][ni][1] + bb.y);
            float2 v1 = make_float2(acc[mi][ni][2] + bb.x, acc[mi][ni][3] + bb.y);
            if (residual) {
                float2 r0v = *(const float2*)(residual + (size_t)r0 * ldc + col);
                float2 r1v = *(const float2*)(residual + (size_t)(r0 + 8) * ldc + col);
                v0.x += r0v.x; v0.y += r0v.y;
                v1.x += r1v.x; v1.y += r1v.y;
            }
            *(float2*)(Cout + (size_t)r0 * ldc + col) = v0;
            *(float2*)(Cout + (size_t)(r0 + 8) * ldc + col) = v1;
        }
    }
}

// fused Q + KV GEMM: bx < 8 -> Q tile; bx >= 8 -> KV tile
__global__ void __launch_bounds__(GTHREADS, 1)
gemm_qkv_kernel(const __nv_bfloat16* __restrict__ xs, const __nv_bfloat16* __restrict__ ys,
                const __nv_bfloat16* __restrict__ wq, const __nv_bfloat16* __restrict__ wkv,
                const float* __restrict__ bq, const float* __restrict__ bkv,
                float* __restrict__ q, float* __restrict__ kv) {
    extern __shared__ __align__(16) char smem[];
    int bx = blockIdx.x;
    if (bx < 8) {
        gemm_core(xs, wq, bq, nullptr, q, C_DIM, blockIdx.y * BM, bx * BN, smem);
    } else {
        gemm_core(ys, wkv, bkv, nullptr, kv, 2 * C_DIM, blockIdx.y * BM, (bx - 8) * BN, smem);
    }
}

__global__ void __launch_bounds__(GTHREADS, 1)
gemm_kernel(const __nv_bfloat16* __restrict__ A, const __nv_bfloat16* __restrict__ B,
            const float* __restrict__ bias, const float* __restrict__ residual,
            float* __restrict__ Cout, int ldc) {
    extern __shared__ __align__(16) char smem[];
    gemm_core(A, B, bias, residual, Cout, ldc, blockIdx.y * BM, blockIdx.x * BN, smem);
}

// -------- per-token [8x8] head-mixing attention; writes split bf16 directly --------
__global__ void __launch_bounds__(256)
attention_kernel(const float* __restrict__ Q, const float* __restrict__ KV,
                 __nv_bfloat16* __restrict__ AOS) {
    int lid = threadIdx.x & 31;
    int t = blockIdx.x * 8 + (threadIdx.x >> 5);
    const float4* q  = (const float4*)(Q  + (size_t)t * C_DIM);
    const float4* kv = (const float4*)(KV + (size_t)t * 2 * C_DIM);
    const float scale = 0.0625f;  // 256^-0.5

    for (int h = 0; h < 8; h++) {
        float4 q0 = q[h * 64 + lid * 2];
        float4 q1 = q[h * 64 + lid * 2 + 1];
        float s[8];
#pragma unroll
        for (int gg = 0; gg < 8; gg++) {
            float4 k0 = kv[gg * 64 + lid * 2];
            float4 k1 = kv[gg * 64 + lid * 2 + 1];
            float d = q0.x * k0.x + q0.y * k0.y + q0.z * k0.z + q0.w * k0.w
                    + q1.x * k1.x + q1.y * k1.y + q1.z * k1.z + q1.w * k1.w;
#pragma unroll
            for (int off = 16; off >= 1; off >>= 1)
                d += __shfl_xor_sync(0xffffffffu, d, off);
            s[gg] = d * scale;
        }
        float m = s[0];
#pragma unroll
        for (int gg = 1; gg < 8; gg++) m = fmaxf(m, s[gg]);
        float e[8], sum = 0.f;
#pragma unroll
        for (int gg = 0; gg < 8; gg++) { e[gg] = __expf(s[gg] - m); sum += e[gg]; }
        float inv = 1.f / sum;
        float f[8];
#pragma unroll
        for (int j = 0; j < 8; j++) f[j] = 0.f;
#pragma unroll
        for (int gg = 0; gg < 8; gg++) {
            float p = e[gg] * inv;
            float4 v0 = kv[512 + gg * 64 + lid * 2];
            float4 v1 = kv[512 + gg * 64 + lid * 2 + 1];
            f[0] += p * v0.x; f[1] += p * v0.y; f[2] += p * v0.z; f[3] += p * v0.w;
            f[4] += p * v1.x; f[5] += p * v1.y; f[6] += p * v1.z; f[7] += p * v1.w;
        }
        uint4 H, L;
        float r[8];
#pragma unroll
        for (int j = 0; j < 8; j++) {
            __nv_bfloat16 hb = __float2bfloat16_rn(f[j]);
            r[j] = f[j] - __bfloat162float(hb);
        }
        H.x = pack_bf16x2(f[0], f[1]); H.y = pack_bf16x2(f[2], f[3]);
        H.z = pack_bf16x2(f[4], f[5]); H.w = pack_bf16x2(f[6], f[7]);
        L.x = pack_bf16x2(r[0], r[1]); L.y = pack_bf16x2(r[2], r[3]);
        L.z = pack_bf16x2(r[4], r[5]); L.w = pack_bf16x2(r[6], r[7]);
        size_t base = (size_t)t * K3 + h * 256 + lid * 8;
        *(uint4*)(AOS + base) = H;
        *(uint4*)(AOS + base + C_DIM) = H;
        *(uint4*)(AOS + base + 2 * C_DIM) = L;
    }
}

// -------- launch --------
extern "C" void kernel_launch(void* const* d_in, const int* in_sizes, int n_in,
                              void* d_out, int out_size) {
    (void)in_sizes; (void)n_in; (void)out_size;
    const float* x  = (const float*)d_in[0];
    const float* y  = (const float*)d_in[1];
    const float* Wq = (const float*)d_in[2];
    const float* bq = (const float*)d_in[3];
    const float* Wk = (const float*)d_in[4];
    const float* bk = (const float*)d_in[5];
    const float* Wv = (const float*)d_in[6];
    const float* bv = (const float*)d_in[7];
    const float* Wo = (const float*)d_in[8];
    const float* bo = (const float*)d_in[9];
    float* out = (float*)d_out;

    cudaFuncSetAttribute(gemm_kernel, cudaFuncAttributeMaxDynamicSharedMemorySize, GEMM_SMEM);
    cudaFuncSetAttribute(gemm_qkv_kernel, cudaFuncAttributeMaxDynamicSharedMemorySize, GEMM_SMEM);

    __nv_bfloat16 *xs, *ys, *aos, *wq, *wkv, *wo;
    float *q, *kv, *bkv;
    cudaGetSymbolAddress((void**)&xs,  g_xs);
    cudaGetSymbolAddress((void**)&ys,  g_ys);
    cudaGetSymbolAddress((void**)&aos, g_aos);
    cudaGetSymbolAddress((void**)&wq,  g_wq);
    cudaGetSymbolAddress((void**)&wkv, g_wkv);
    cudaGetSymbolAddress((void**)&wo,  g_wo);
    cudaGetSymbolAddress((void**)&q,   g_q);
    cudaGetSymbolAddress((void**)&kv,  g_kv);
    cudaGetSymbolAddress((void**)&bkv, g_bkv);

    const int actBlocks = (T_TOK * C_DIM) / 256;   // 32768 per tensor
    const int wgtBlocks = (C_DIM * C_DIM) / 256;   // 16384 per tensor

    // launch order chosen so ncu (-s 5) profiles the O GEMM (index 5)
    concat_bias_kernel<<<16, 256>>>(bk, bv, bkv);                            // 0
    split_acts_kernel<<<dim3(actBlocks, 2), 256>>>(x, y, xs, ys);            // 1
    split_wgts_kernel<<<dim3(wgtBlocks, 4), 256>>>(Wq, Wk, Wv, Wo,
                                                   wq, wkv, wo);             // 2
    gemm_qkv_kernel<<<dim3(24, 64), GTHREADS, GEMM_SMEM>>>(xs, ys, wq, wkv,
                                                           bq, bkv, q, kv);  // 3
    attention_kernel<<<T_TOK / 8, 256>>>(q, kv, aos);                        // 4
    gemm_kernel<<<dim3(8, 64), GTHREADS, GEMM_SMEM>>>(aos, wo, bo, x, out,
                                                      C_DIM);                // 5
}

// round 10
// speedup vs baseline: 2.0093x; 2.0093x over previous
#include <cuda_runtime.h>
#include <cuda_fp16.h>
#include <cstdint>

static constexpr int T_TOK = 8192;
static constexpr int C_DIM = 2048;
static constexpr int K2 = 2 * C_DIM;       // 4096 : [hi|lo] fp16 split-concat K
static constexpr int BM = 128;
static constexpr int BN = 256;
static constexpr int BK = 64;              // fp16 per K-chunk (128B rows)
static constexpr int NKCH = K2 / BK;       // 64
static constexpr int ROW_BYTES = 144;      // 128B data + 16B pad (conflict-free ldmatrix)
static constexpr int AROWS = BM;
static constexpr int STAGE_ROWS = BM + BN; // 384
static constexpr int STAGE_BYTES = STAGE_ROWS * ROW_BYTES;  // 55296
static constexpr int STAGES = 4;
static constexpr int GEMM_SMEM = STAGES * STAGE_BYTES;      // 221184
static constexpr int GTHREADS = 512;       // 16 warps: 2 over M x 8 over N

// -------- scratch (static __device__; no allocation allowed) --------
__device__ __half g_xs [(size_t)T_TOK * K2];
__device__ __half g_ys [(size_t)T_TOK * K2];
__device__ __half g_aos[(size_t)T_TOK * K2];
__device__ __half g_wq [(size_t)C_DIM * K2];
__device__ __half g_wkv[(size_t)(2 * C_DIM) * K2];
__device__ __half g_wo [(size_t)C_DIM * K2];
__device__ float g_q  [(size_t)T_TOK * C_DIM];
__device__ float g_kv [(size_t)T_TOK * 2 * C_DIM];
__device__ float g_bkv[2 * C_DIM];

// -------- PTX helpers (sm_80+ only; no 'a'-suffix features) --------
__device__ __forceinline__ uint32_t smem_u32(const void* p) {
    uint32_t a;
    asm("{ .reg .u64 t; cvta.to.shared.u64 t, %1; cvt.u32.u64 %0, t; }" : "=r"(a) : "l"(p));
    return a;
}
#define CP_ASYNC16(s, g) \
    asm volatile("cp.async.cg.shared.global [%0], [%1], 16;" :: "r"((uint32_t)(s)), "l"(g) : "memory")
#define CP_COMMIT() asm volatile("cp.async.commit_group;" ::: "memory")

#define LDSM4(r, addr) \
    asm volatile("ldmatrix.sync.aligned.m8n8.x4.shared.b16 {%0,%1,%2,%3}, [%4];" \
        : "=r"((r)[0]), "=r"((r)[1]), "=r"((r)[2]), "=r"((r)[3]) : "r"(addr))

#define MMA16816(d, a, b0, b1) \
    asm volatile("mma.sync.aligned.m16n8k16.row.col.f32.f16.f16.f32 " \
        "{%0,%1,%2,%3}, {%4,%5,%6,%7}, {%8,%9}, {%0,%1,%2,%3};" \
        : "+f"((d)[0]), "+f"((d)[1]), "+f"((d)[2]), "+f"((d)[3]) \
        : "r"((a)[0]), "r"((a)[1]), "r"((a)[2]), "r"((a)[3]), "r"(b0), "r"(b1))

__device__ __forceinline__ uint32_t pack_h2(float x, float y) {
    __half2 h = __floats2half2_rn(x, y);
    return *(uint32_t*)&h;
}

// -------- fp16 2-term split conversions --------
// acts: fp32 -> [hi | lo]   (a = hi + lo to ~2^-22)
__global__ void split_acts_kernel(const float* __restrict__ x, const float* __restrict__ y,
                                  __half* __restrict__ xs, __half* __restrict__ ys) {
    const float* src = blockIdx.y ? y : x;
    __half* dst = blockIdx.y ? ys : xs;
    size_t i = (size_t)blockIdx.x * blockDim.x + threadIdx.x;
    int r = (int)(i >> 11);
    int c = (int)(i & (C_DIM - 1));
    float v = src[i];
    __half hi = __float2half_rn(v);
    __half lo = __float2half_rn(v - __half2float(hi));
    size_t o = (size_t)r * K2 + c;
    dst[o] = hi; dst[o + C_DIM] = lo;
}
// weights: fp32 -> [hi | hi]  (both K-halves multiply by w_hi)
__global__ void split_wgts_kernel(const float* __restrict__ Wq, const float* __restrict__ Wk,
                                  const float* __restrict__ Wv, const float* __restrict__ Wo,
                                  __half* __restrict__ wq, __half* __restrict__ wkv,
                                  __half* __restrict__ wo) {
    int sel = blockIdx.y;
    const float* src = (sel == 0) ? Wq : (sel == 1) ? Wk : (sel == 2) ? Wv : Wo;
    __half* dst = (sel == 0) ? wq : (sel == 1) ? wkv
                : (sel == 2) ? wkv + (size_t)C_DIM * K2 : wo;
    size_t i = (size_t)blockIdx.x * blockDim.x + threadIdx.x;
    int r = (int)(i >> 11);
    int c = (int)(i & (C_DIM - 1));
    __half hi = __float2half_rn(src[i]);
    size_t o = (size_t)r * K2 + c;
    dst[o] = hi; dst[o + C_DIM] = hi;
}
__global__ void concat_bias_kernel(const float* __restrict__ bk,
                                   const float* __restrict__ bv,
                                   float* __restrict__ dst) {
    int i = blockIdx.x * blockDim.x + threadIdx.x;
    dst[i] = (i < C_DIM) ? bk[i] : bv[i - C_DIM];
}

// -------- HMMA GEMM core (512 threads): C = A[M,K2] @ B[N,K2]^T + bias (+res) --------
__device__ __forceinline__ void load_tiles_part(const __half* __restrict__ A,
                                                const __half* __restrict__ B,
                                                int rowA0, int rowB0, int k0,
                                                uint32_t sbase, int tid, int part) {
    // 3072 x 16B chunks / 512 threads = 6 iters; parts 0..2, 2 iters each
    if (part >= 3) return;
#pragma unroll
    for (int i = 2 * part; i < 2 * part + 2; i++) {
        int idx = i * GTHREADS + tid;
        int row = idx >> 3;
        int c = idx & 7;
        const __half* g = (row < AROWS)
            ? A + (size_t)(rowA0 + row) * K2 + (k0 + c * 8)
            : B + (size_t)(rowB0 + row - AROWS) * K2 + (k0 + c * 8);
        CP_ASYNC16(sbase + row * ROW_BYTES + c * 16, g);
    }
}
__device__ __forceinline__ void load_tiles(const __half* __restrict__ A,
                                           const __half* __restrict__ B,
                                           int rowA0, int rowB0, int k0,
                                           uint32_t sbase, int tid) {
#pragma unroll
    for (int p = 0; p < 3; p++)
        load_tiles_part(A, B, rowA0, rowB0, k0, sbase, tid, p);
}

__device__ __forceinline__ void gemm_core(const __half* __restrict__ A,
                                          const __half* __restrict__ B,
                                          const float* __restrict__ bias,
                                          const float* __restrict__ residual,
                                          float* __restrict__ Cout, int ldc,
                                          int rowA0, int rowB0, char* smem) {
    uint32_t sb = smem_u32(smem);
    int tid = threadIdx.x;
    int wid = tid >> 5, lid = tid & 31;
    int warp_m = wid & 1;                   // 2 warps over M (64 rows each)
    int warp_n = wid >> 1;                  // 8 warps over N (32 cols each)

    float acc[4][4][4];
#pragma unroll
    for (int mi = 0; mi < 4; mi++)
#pragma unroll
        for (int ni = 0; ni < 4; ni++)
#pragma unroll
            for (int e = 0; e < 4; e++) acc[mi][ni][e] = 0.f;

#pragma unroll
    for (int s = 0; s < STAGES - 1; s++) {
        load_tiles(A, B, rowA0, rowB0, s * BK, sb + s * STAGE_BYTES, tid);
        CP_COMMIT();
    }

    uint32_t a_base = sb + (warp_m * 64 + (lid & 15)) * ROW_BYTES + ((lid >> 4) << 4);
    int g = lid >> 3;
    uint32_t b_base = sb + (AROWS + warp_n * 32 + ((g >> 1) << 3) + (lid & 7)) * ROW_BYTES
                         + ((g & 1) << 4);

    for (int k = 0; k < NKCH; k++) {
        int rem = NKCH - 1 - k;
        if (rem > STAGES - 2) rem = STAGES - 2;
        switch (rem) {
            case 0: asm volatile("cp.async.wait_group 0;" ::: "memory"); break;
            case 1: asm volatile("cp.async.wait_group 1;" ::: "memory"); break;
            default: asm volatile("cp.async.wait_group 2;" ::: "memory"); break;
        }
        __syncthreads();

        uint32_t sa  = a_base + (k % STAGES) * STAGE_BYTES;
        uint32_t sbb = b_base + (k % STAGES) * STAGE_BYTES;

        int pk = k + STAGES - 1;
        bool do_pf = (pk < NKCH);
        uint32_t pf_base = sb + (pk % STAGES) * STAGE_BYTES;
        int pf_k0 = pk * BK;

#pragma unroll
        for (int ks = 0; ks < 4; ks++) {    // 4 x k16 per BK=64
            uint32_t afr[4][4], bfr[2][4];
#pragma unroll
            for (int mi = 0; mi < 4; mi++)
                LDSM4(afr[mi], sa + mi * 16 * ROW_BYTES + ks * 32);
#pragma unroll
            for (int ni2 = 0; ni2 < 2; ni2++)
                LDSM4(bfr[ni2], sbb + ni2 * 16 * ROW_BYTES + ks * 32);
            // spread prefetch across ks steps
            if (do_pf) {
                load_tiles_part(A, B, rowA0, rowB0, pf_k0, pf_base, tid, ks);
                if (ks == 3) CP_COMMIT();
            }
#pragma unroll
            for (int mi = 0; mi < 4; mi++)
#pragma unroll
                for (int ni2 = 0; ni2 < 2; ni2++) {
                    MMA16816(acc[mi][2 * ni2],     afr[mi], bfr[ni2][0], bfr[ni2][1]);
                    MMA16816(acc[mi][2 * ni2 + 1], afr[mi], bfr[ni2][2], bfr[ni2][3]);
                }
        }
    }

    int qrow = lid >> 2, qcol = (lid & 3) * 2;
#pragma unroll
    for (int mi = 0; mi < 4; mi++) {
#pragma unroll
        for (int ni = 0; ni < 4; ni++) {
            int r0 = rowA0 + warp_m * 64 + mi * 16 + qrow;
            int col = rowB0 + warp_n * 32 + ni * 8 + qcol;
            float2 bb = *(const float2*)(bias + col);
            float2 v0 = make_float2(acc[mi][ni][0] + bb.x, acc[mi][ni][1] + bb.y);
            float2 v1 = make_float2(acc[mi][ni][2] + bb.x, acc[mi][ni][3] + bb.y);
            if (residual) {
                float2 r0v = *(const float2*)(residual + (size_t)r0 * ldc + col);
                float2 r1v = *(const float2*)(residual + (size_t)(r0 + 8) * ldc + col);
                v0.x += r0v.x; v0.y += r0v.y;
                v1.x += r1v.x; v1.y += r1v.y;
            }
            *(float2*)(Cout + (size_t)r0 * ldc + col) = v0;
            *(float2*)(Cout + (size_t)(r0 + 8) * ldc + col) = v1;
        }
    }
}

// fused Q + KV GEMM: bx < 8 -> Q tile; bx >= 8 -> KV tile
__global__ void __launch_bounds__(GTHREADS, 1)
gemm_qkv_kernel(const __half* __restrict__ xs, const __half* __restrict__ ys,
                const __half* __restrict__ wq, const __half* __restrict__ wkv,
                const float* __restrict__ bq, const float* __restrict__ bkv,
                float* __restrict__ q, float* __restrict__ kv) {
    extern __shared__ __align__(16) char smem[];
    int bx = blockIdx.x;
    if (bx < 8) {
        gemm_core(xs, wq, bq, nullptr, q, C_DIM, blockIdx.y * BM, bx * BN, smem);
    } else {
        gemm_core(ys, wkv, bkv, nullptr, kv, 2 * C_DIM, blockIdx.y * BM, (bx - 8) * BN, smem);
    }
}

__global__ void __launch_bounds__(GTHREADS, 1)
gemm_kernel(const __half* __restrict__ A, const __half* __restrict__ B,
            const float* __restrict__ bias, const float* __restrict__ residual,
            float* __restrict__ Cout, int ldc) {
    extern __shared__ __align__(16) char smem[];
    gemm_core(A, B, bias, residual, Cout, ldc, blockIdx.y * BM, blockIdx.x * BN, smem);
}

// -------- per-token [8x8] head-mixing attention; writes fp16 [hi|lo] directly --------
__global__ void __launch_bounds__(256)
attention_kernel(const float* __restrict__ Q, const float* __restrict__ KV,
                 __half* __restrict__ AOS) {
    int lid = threadIdx.x & 31;
    int t = blockIdx.x * 8 + (threadIdx.x >> 5);
    const float4* q  = (const float4*)(Q  + (size_t)t * C_DIM);
    const float4* kv = (const float4*)(KV + (size_t)t * 2 * C_DIM);
    const float scale = 0.0625f;  // 256^-0.5

    for (int h = 0; h < 8; h++) {
        float4 q0 = q[h * 64 + lid * 2];
        float4 q1 = q[h * 64 + lid * 2 + 1];
        float s[8];
#pragma unroll
        for (int gg = 0; gg < 8; gg++) {
            float4 k0 = kv[gg * 64 + lid * 2];
            float4 k1 = kv[gg * 64 + lid * 2 + 1];
            float d = q0.x * k0.x + q0.y * k0.y + q0.z * k0.z + q0.w * k0.w
                    + q1.x * k1.x + q1.y * k1.y + q1.z * k1.z + q1.w * k1.w;
#pragma unroll
            for (int off = 16; off >= 1; off >>= 1)
                d += __shfl_xor_sync(0xffffffffu, d, off);
            s[gg] = d * scale;
        }
        float m = s[0];
#pragma unroll
        for (int gg = 1; gg < 8; gg++) m = fmaxf(m, s[gg]);
        float e[8], sum = 0.f;
#pragma unroll
        for (int gg = 0; gg < 8; gg++) { e[gg] = __expf(s[gg] - m); sum += e[gg]; }
        float inv = 1.f / sum;
        float f[8];
#pragma unroll
        for (int j = 0; j < 8; j++) f[j] = 0.f;
#pragma unroll
        for (int gg = 0; gg < 8; gg++) {
            float p = e[gg] * inv;
            float4 v0 = kv[512 + gg * 64 + lid * 2];
            float4 v1 = kv[512 + gg * 64 + lid * 2 + 1];
            f[0] += p * v0.x; f[1] += p * v0.y; f[2] += p * v0.z; f[3] += p * v0.w;
            f[4] += p * v1.x; f[5] += p * v1.y; f[6] += p * v1.z; f[7] += p * v1.w;
        }
        uint4 H, L;
        float r[8];
#pragma unroll
        for (int j = 0; j < 8; j++) {
            __half hb = __float2half_rn(f[j]);
            r[j] = f[j] - __half2float(hb);
        }
        H.x = pack_h2(f[0], f[1]); H.y = pack_h2(f[2], f[3]);
        H.z = pack_h2(f[4], f[5]); H.w = pack_h2(f[6], f[7]);
        L.x = pack_h2(r[0], r[1]); L.y = pack_h2(r[2], r[3]);
        L.z = pack_h2(r[4], r[5]); L.w = pack_h2(r[6], r[7]);
        size_t base = (size_t)t * K2 + h * 256 + lid * 8;
        *(uint4*)(AOS + base) = H;
        *(uint4*)(AOS + base + C_DIM) = L;
    }
}

// -------- launch --------
extern "C" void kernel_launch(void* const* d_in, const int* in_sizes, int n_in,
                              void* d_out, int out_size) {
    (void)in_sizes; (void)n_in; (void)out_size;
    const float* x  = (const float*)d_in[0];
    const float* y  = (const float*)d_in[1];
    const float* Wq = (const float*)d_in[2];
    const float* bq = (const float*)d_in[3];
    const float* Wk = (const float*)d_in[4];
    const float* bk = (const float*)d_in[5];
    const float* Wv = (const float*)d_in[6];
    const float* bv = (const float*)d_in[7];
    const float* Wo = (const float*)d_in[8];
    const float* bo = (const float*)d_in[9];
    float* out = (float*)d_out;

    cudaFuncSetAttribute(gemm_kernel, cudaFuncAttributeMaxDynamicSharedMemorySize, GEMM_SMEM);
    cudaFuncSetAttribute(gemm_qkv_kernel, cudaFuncAttributeMaxDynamicSharedMemorySize, GEMM_SMEM);

    __half *xs, *ys, *aos, *wq, *wkv, *wo;
    float *q, *kv, *bkv;
    cudaGetSymbolAddress((void**)&xs,  g_xs);
    cudaGetSymbolAddress((void**)&ys,  g_ys);
    cudaGetSymbolAddress((void**)&aos, g_aos);
    cudaGetSymbolAddress((void**)&wq,  g_wq);
    cudaGetSymbolAddress((void**)&wkv, g_wkv);
    cudaGetSymbolAddress((void**)&wo,  g_wo);
    cudaGetSymbolAddress((void**)&q,   g_q);
    cudaGetSymbolAddress((void**)&kv,  g_kv);
    cudaGetSymbolAddress((void**)&bkv, g_bkv);

    const int actBlocks = (T_TOK * C_DIM) / 256;   // 32768 per tensor
    const int wgtBlocks = (C_DIM * C_DIM) / 256;   // 16384 per tensor

    // launch order chosen so ncu (-s 5) profiles the O GEMM (index 5)
    concat_bias_kernel<<<16, 256>>>(bk, bv, bkv);                            // 0
    split_acts_kernel<<<dim3(actBlocks, 2), 256>>>(x, y, xs, ys);            // 1
    split_wgts_kernel<<<dim3(wgtBlocks, 4), 256>>>(Wq, Wk, Wv, Wo,
                                                   wq, wkv, wo);             // 2
    gemm_qkv_kernel<<<dim3(24, 64), GTHREADS, GEMM_SMEM>>>(xs, ys, wq, wkv,
                                                           bq, bkv, q, kv);  // 3
    attention_kernel<<<T_TOK / 8, 256>>>(q, kv, aos);                        // 4
    gemm_kernel<<<dim3(8, 64), GTHREADS, GEMM_SMEM>>>(aos, wo, bo, x, out,
                                                      C_DIM);                // 5
}

// round 12
// speedup vs baseline: 3.6973x; 1.8401x over previous
#include <cuda_runtime.h>
#include <cuda_fp16.h>
#include <cstdint>

static constexpr int T_TOK = 8192;
static constexpr int C_DIM = 2048;
static constexpr int KDIM = C_DIM;         // plain fp16 GEMM, K = 2048
static constexpr int BM = 128;
static constexpr int BN = 256;
static constexpr int BK = 64;              // fp16 per K-chunk (128B rows)
static constexpr int NKCH = KDIM / BK;     // 32
static constexpr int ROW_BYTES = 144;      // 128B data + 16B pad (conflict-free ldmatrix)
static constexpr int AROWS = BM;
static constexpr int STAGE_ROWS = BM + BN; // 384
static constexpr int STAGE_BYTES = STAGE_ROWS * ROW_BYTES;  // 55296
static constexpr int STAGES = 4;
static constexpr int GEMM_SMEM = STAGES * STAGE_BYTES;      // 221184
static constexpr int GTHREADS = 512;       // 16 warps: 2 over M x 8 over N

// -------- scratch (static __device__; no allocation allowed) --------
__device__ __half g_xs [(size_t)T_TOK * C_DIM];
__device__ __half g_ys [(size_t)T_TOK * C_DIM];
__device__ __half g_aos[(size_t)T_TOK * C_DIM];
__device__ __half g_wq [(size_t)C_DIM * C_DIM];
__device__ __half g_wkv[(size_t)(2 * C_DIM) * C_DIM];
__device__ __half g_wo [(size_t)C_DIM * C_DIM];
__device__ float g_q  [(size_t)T_TOK * C_DIM];
__device__ float g_kv [(size_t)T_TOK * 2 * C_DIM];
__device__ float g_bkv[2 * C_DIM];

// -------- PTX helpers (sm_80+ only; no 'a'-suffix features) --------
__device__ __forceinline__ uint32_t smem_u32(const void* p) {
    uint32_t a;
    asm("{ .reg .u64 t; cvta.to.shared.u64 t, %1; cvt.u32.u64 %0, t; }" : "=r"(a) : "l"(p));
    return a;
}
#define CP_ASYNC16(s, g) \
    asm volatile("cp.async.cg.shared.global [%0], [%1], 16;" :: "r"((uint32_t)(s)), "l"(g) : "memory")
#define CP_COMMIT() asm volatile("cp.async.commit_group;" ::: "memory")

#define LDSM4(r, addr) \
    asm volatile("ldmatrix.sync.aligned.m8n8.x4.shared.b16 {%0,%1,%2,%3}, [%4];" \
        : "=r"((r)[0]), "=r"((r)[1]), "=r"((r)[2]), "=r"((r)[3]) : "r"(addr))

#define MMA16816(d, a, b0, b1) \
    asm volatile("mma.sync.aligned.m16n8k16.row.col.f32.f16.f16.f32 " \
        "{%0,%1,%2,%3}, {%4,%5,%6,%7}, {%8,%9}, {%0,%1,%2,%3};" \
        : "+f"((d)[0]), "+f"((d)[1]), "+f"((d)[2]), "+f"((d)[3]) \
        : "r"((a)[0]), "r"((a)[1]), "r"((a)[2]), "r"((a)[3]), "r"(b0), "r"(b1))

__device__ __forceinline__ uint32_t pack_h2(float x, float y) {
    __half2 h = __floats2half2_rn(x, y);
    return *(uint32_t*)&h;
}

// -------- fp32 -> fp16 conversions (vectorized: 4 floats -> 4 halves per thread) --------
__global__ void convert_acts_kernel(const float* __restrict__ x, const float* __restrict__ y,
                                    __half* __restrict__ xs, __half* __restrict__ ys) {
    const float* src = blockIdx.y ? y : x;
    __half* dst = blockIdx.y ? ys : xs;
    size_t i = ((size_t)blockIdx.x * blockDim.x + threadIdx.x) * 4;
    float4 v = *(const float4*)(src + i);
    uint2 o;
    o.x = pack_h2(v.x, v.y);
    o.y = pack_h2(v.z, v.w);
    *(uint2*)(dst + i) = o;
}
__global__ void convert_wgts_kernel(const float* __restrict__ Wq, const float* __restrict__ Wk,
                                    const float* __restrict__ Wv, const float* __restrict__ Wo,
                                    __half* __restrict__ wq, __half* __restrict__ wkv,
                                    __half* __restrict__ wo) {
    int sel = blockIdx.y;
    const float* src = (sel == 0) ? Wq : (sel == 1) ? Wk : (sel == 2) ? Wv : Wo;
    __half* dst = (sel == 0) ? wq : (sel == 1) ? wkv
                : (sel == 2) ? wkv + (size_t)C_DIM * C_DIM : wo;
    size_t i = ((size_t)blockIdx.x * blockDim.x + threadIdx.x) * 4;
    float4 v = *(const float4*)(src + i);
    uint2 o;
    o.x = pack_h2(v.x, v.y);
    o.y = pack_h2(v.z, v.w);
    *(uint2*)(dst + i) = o;
}
__global__ void concat_bias_kernel(const float* __restrict__ bk,
                                   const float* __restrict__ bv,
                                   float* __restrict__ dst) {
    int i = blockIdx.x * blockDim.x + threadIdx.x;
    dst[i] = (i < C_DIM) ? bk[i] : bv[i - C_DIM];
}

// -------- HMMA GEMM core (512 threads): C = A[M,K] @ B[N,K]^T + bias (+res) --------
__device__ __forceinline__ void load_tiles_part(const __half* __restrict__ A,
                                                const __half* __restrict__ B,
                                                int rowA0, int rowB0, int k0,
                                                uint32_t sbase, int tid, int part) {
    // 3072 x 16B chunks / 512 threads = 6 iters; parts 0..2, 2 iters each
    if (part >= 3) return;
#pragma unroll
    for (int i = 2 * part; i < 2 * part + 2; i++) {
        int idx = i * GTHREADS + tid;
        int row = idx >> 3;
        int c = idx & 7;
        const __half* g = (row < AROWS)
            ? A + (size_t)(rowA0 + row) * KDIM + (k0 + c * 8)
            : B + (size_t)(rowB0 + row - AROWS) * KDIM + (k0 + c * 8);
        CP_ASYNC16(sbase + row * ROW_BYTES + c * 16, g);
    }
}
__device__ __forceinline__ void load_tiles(const __half* __restrict__ A,
                                           const __half* __restrict__ B,
                                           int rowA0, int rowB0, int k0,
                                           uint32_t sbase, int tid) {
#pragma unroll
    for (int p = 0; p < 3; p++)
        load_tiles_part(A, B, rowA0, rowB0, k0, sbase, tid, p);
}

__device__ __forceinline__ void gemm_core(const __half* __restrict__ A,
                                          const __half* __restrict__ B,
                                          const float* __restrict__ bias,
                                          const float* __restrict__ residual,
                                          float* __restrict__ Cout, int ldc,
                                          int rowA0, int rowB0, char* smem) {
    uint32_t sb = smem_u32(smem);
    int tid = threadIdx.x;
    int wid = tid >> 5, lid = tid & 31;
    int warp_m = wid & 1;                   // 2 warps over M (64 rows each)
    int warp_n = wid >> 1;                  // 8 warps over N (32 cols each)

    float acc[4][4][4];
#pragma unroll
    for (int mi = 0; mi < 4; mi++)
#pragma unroll
        for (int ni = 0; ni < 4; ni++)
#pragma unroll
            for (int e = 0; e < 4; e++) acc[mi][ni][e] = 0.f;

#pragma unroll
    for (int s = 0; s < STAGES - 1; s++) {
        load_tiles(A, B, rowA0, rowB0, s * BK, sb + s * STAGE_BYTES, tid);
        CP_COMMIT();
    }

    uint32_t a_base = sb + (warp_m * 64 + (lid & 15)) * ROW_BYTES + ((lid >> 4) << 4);
    int g = lid >> 3;
    uint32_t b_base = sb + (AROWS + warp_n * 32 + ((g >> 1) << 3) + (lid & 7)) * ROW_BYTES
                         + ((g & 1) << 4);

    for (int k = 0; k < NKCH; k++) {
        int rem = NKCH - 1 - k;
        if (rem > STAGES - 2) rem = STAGES - 2;
        switch (rem) {
            case 0: asm volatile("cp.async.wait_group 0;" ::: "memory"); break;
            case 1: asm volatile("cp.async.wait_group 1;" ::: "memory"); break;
            default: asm volatile("cp.async.wait_group 2;" ::: "memory"); break;
        }
        __syncthreads();

        uint32_t sa  = a_base + (k % STAGES) * STAGE_BYTES;
        uint32_t sbb = b_base + (k % STAGES) * STAGE_BYTES;

        int pk = k + STAGES - 1;
        bool do_pf = (pk < NKCH);
        uint32_t pf_base = sb + (pk % STAGES) * STAGE_BYTES;
        int pf_k0 = pk * BK;

#pragma unroll
        for (int ks = 0; ks < 4; ks++) {    // 4 x k16 per BK=64
            uint32_t afr[4][4], bfr[2][4];
#pragma unroll
            for (int mi = 0; mi < 4; mi++)
                LDSM4(afr[mi], sa + mi * 16 * ROW_BYTES + ks * 32);
#pragma unroll
            for (int ni2 = 0; ni2 < 2; ni2++)
                LDSM4(bfr[ni2], sbb + ni2 * 16 * ROW_BYTES + ks * 32);
            // spread prefetch across ks steps
            if (do_pf) {
                load_tiles_part(A, B, rowA0, rowB0, pf_k0, pf_base, tid, ks);
                if (ks == 3) CP_COMMIT();
            }
#pragma unroll
            for (int mi = 0; mi < 4; mi++)
#pragma unroll
                for (int ni2 = 0; ni2 < 2; ni2++) {
                    MMA16816(acc[mi][2 * ni2],     afr[mi], bfr[ni2][0], bfr[ni2][1]);
                    MMA16816(acc[mi][2 * ni2 + 1], afr[mi], bfr[ni2][2], bfr[ni2][3]);
                }
        }
    }

    int qrow = lid >> 2, qcol = (lid & 3) * 2;
#pragma unroll
    for (int mi = 0; mi < 4; mi++) {
#pragma unroll
        for (int ni = 0; ni < 4; ni++) {
            int r0 = rowA0 + warp_m * 64 + mi * 16 + qrow;
            int col = rowB0 + warp_n * 32 + ni * 8 + qcol;
            float2 bb = *(const float2*)(bias + col);
            float2 v0 = make_float2(acc[mi][ni][0] + bb.x, acc[mi][ni][1] + bb.y);
            float2 v1 = make_float2(acc[mi][ni][2] + bb.x, acc[mi][ni][3] + bb.y);
            if (residual) {
                float2 r0v = *(const float2*)(residual + (size_t)r0 * ldc + col);
                float2 r1v = *(const float2*)(residual + (size_t)(r0 + 8) * ldc + col);
                v0.x += r0v.x; v0.y += r0v.y;
                v1.x += r1v.x; v1.y += r1v.y;
            }
            *(float2*)(Cout + (size_t)r0 * ldc + col) = v0;
            *(float2*)(Cout + (size_t)(r0 + 8) * ldc + col) = v1;
        }
    }
}

// fused Q + KV GEMM: bx < 8 -> Q tile; bx >= 8 -> KV tile
__global__ void __launch_bounds__(GTHREADS, 1)
gemm_qkv_kernel(const __half* __restrict__ xs, const __half* __restrict__ ys,
                const __half* __restrict__ wq, const __half* __restrict__ wkv,
                const float* __restrict__ bq, const float* __restrict__ bkv,
                float* __restrict__ q, float* __restrict__ kv) {
    extern __shared__ __align__(16) char smem[];
    int bx = blockIdx.x;
    if (bx < 8) {
        gemm_core(xs, wq, bq, nullptr, q, C_DIM, blockIdx.y * BM, bx * BN, smem);
    } else {
        gemm_core(ys, wkv, bkv, nullptr, kv, 2 * C_DIM, blockIdx.y * BM, (bx - 8) * BN, smem);
    }
}

__global__ void __launch_bounds__(GTHREADS, 1)
gemm_kernel(const __half* __restrict__ A, const __half* __restrict__ B,
            const float* __restrict__ bias, const float* __restrict__ residual,
            float* __restrict__ Cout, int ldc) {
    extern __shared__ __align__(16) char smem[];
    gemm_core(A, B, bias, residual, Cout, ldc, blockIdx.y * BM, blockIdx.x * BN, smem);
}

// -------- per-token [8x8] head-mixing attention; writes fp16 directly --------
__global__ void __launch_bounds__(256)
attention_kernel(const float* __restrict__ Q, const float* __restrict__ KV,
                 __half* __restrict__ AOS) {
    int lid = threadIdx.x & 31;
    int t = blockIdx.x * 8 + (threadIdx.x >> 5);
    const float4* q  = (const float4*)(Q  + (size_t)t * C_DIM);
    const float4* kv = (const float4*)(KV + (size_t)t * 2 * C_DIM);
    const float scale = 0.0625f;  // 256^-0.5

    for (int h = 0; h < 8; h++) {
        float4 q0 = q[h * 64 + lid * 2];
        float4 q1 = q[h * 64 + lid * 2 + 1];
        float s[8];
#pragma unroll
        for (int gg = 0; gg < 8; gg++) {
            float4 k0 = kv[gg * 64 + lid * 2];
            float4 k1 = kv[gg * 64 + lid * 2 + 1];
            float d = q0.x * k0.x + q0.y * k0.y + q0.z * k0.z + q0.w * k0.w
                    + q1.x * k1.x + q1.y * k1.y + q1.z * k1.z + q1.w * k1.w;
#pragma unroll
            for (int off = 16; off >= 1; off >>= 1)
                d += __shfl_xor_sync(0xffffffffu, d, off);
            s[gg] = d * scale;
        }
        float m = s[0];
#pragma unroll
        for (int gg = 1; gg < 8; gg++) m = fmaxf(m, s[gg]);
        float e[8], sum = 0.f;
#pragma unroll
        for (int gg = 0; gg < 8; gg++) { e[gg] = __expf(s[gg] - m); sum += e[gg]; }
        float inv = 1.f / sum;
        float f[8];
#pragma unroll
        for (int j = 0; j < 8; j++) f[j] = 0.f;
#pragma unroll
        for (int gg = 0; gg < 8; gg++) {
            float p = e[gg] * inv;
            float4 v0 = kv[512 + gg * 64 + lid * 2];
            float4 v1 = kv[512 + gg * 64 + lid * 2 + 1];
            f[0] += p * v0.x; f[1] += p * v0.y; f[2] += p * v0.z; f[3] += p * v0.w;
            f[4] += p * v1.x; f[5] += p * v1.y; f[6] += p * v1.z; f[7] += p * v1.w;
        }
        uint4 H;
        H.x = pack_h2(f[0], f[1]); H.y = pack_h2(f[2], f[3]);
        H.z = pack_h2(f[4], f[5]); H.w = pack_h2(f[6], f[7]);
        size_t base = (size_t)t * C_DIM + h * 256 + lid * 8;
        *(uint4*)(AOS + base) = H;
    }
}

// -------- launch --------
extern "C" void kernel_launch(void* const* d_in, const int* in_sizes, int n_in,
                              void* d_out, int out_size) {
    (void)in_sizes; (void)n_in; (void)out_size;
    const float* x  = (const float*)d_in[0];
    const float* y  = (const float*)d_in[1];
    const float* Wq = (const float*)d_in[2];
    const float* bq = (const float*)d_in[3];
    const float* Wk = (const float*)d_in[4];
    const float* bk = (const float*)d_in[5];
    const float* Wv = (const float*)d_in[6];
    const float* bv = (const float*)d_in[7];
    const float* Wo = (const float*)d_in[8];
    const float* bo = (const float*)d_in[9];
    float* out = (float*)d_out;

    cudaFuncSetAttribute(gemm_kernel, cudaFuncAttributeMaxDynamicSharedMemorySize, GEMM_SMEM);
    cudaFuncSetAttribute(gemm_qkv_kernel, cudaFuncAttributeMaxDynamicSharedMemorySize, GEMM_SMEM);

    __half *xs, *ys, *aos, *wq, *wkv, *wo;
    float *q, *kv, *bkv;
    cudaGetSymbolAddress((void**)&xs,  g_xs);
    cudaGetSymbolAddress((void**)&ys,  g_ys);
    cudaGetSymbolAddress((void**)&aos, g_aos);
    cudaGetSymbolAddress((void**)&wq,  g_wq);
    cudaGetSymbolAddress((void**)&wkv, g_wkv);
    cudaGetSymbolAddress((void**)&wo,  g_wo);
    cudaGetSymbolAddress((void**)&q,   g_q);
    cudaGetSymbolAddress((void**)&kv,  g_kv);
    cudaGetSymbolAddress((void**)&bkv, g_bkv);

    const int actBlocks = (T_TOK * C_DIM) / (256 * 4);   // 8192 per tensor
    const int wgtBlocks = (C_DIM * C_DIM) / (256 * 4);   // 4096 per tensor

    // launch order chosen so ncu (-s 5) profiles the O GEMM (index 5)
    concat_bias_kernel<<<16, 256>>>(bk, bv, bkv);                            // 0
    convert_acts_kernel<<<dim3(actBlocks, 2), 256>>>(x, y, xs, ys);          // 1
    convert_wgts_kernel<<<dim3(wgtBlocks, 4), 256>>>(Wq, Wk, Wv, Wo,
                                                     wq, wkv, wo);           // 2
    gemm_qkv_kernel<<<dim3(24, 64), GTHREADS, GEMM_SMEM>>>(xs, ys, wq, wkv,
                                                           bq, bkv, q, kv);  // 3
    attention_kernel<<<T_TOK / 8, 256>>>(q, kv, aos);                        // 4
    gemm_kernel<<<dim3(8, 64), GTHREADS, GEMM_SMEM>>>(aos, wo, bo, x, out,
                                                      C_DIM);                // 5
}

// round 14
// speedup vs baseline: 4.0629x; 1.0989x over previous
#include <cuda_runtime.h>
#include <cuda_fp16.h>
#include <cstdint>

static constexpr int T_TOK = 8192;
static constexpr int C_DIM = 2048;
static constexpr int KDIM = C_DIM;         // plain fp16 GEMM, K = 2048
static constexpr int BM = 128;
static constexpr int BN = 128;
static constexpr int BK = 64;              // fp16 per K-chunk (128B rows)
static constexpr int NKCH = KDIM / BK;     // 32
static constexpr int ROW_BYTES = 144;      // 128B data + 16B pad (conflict-free ldmatrix)
static constexpr int AROWS = BM;
static constexpr int STAGE_ROWS = BM + BN; // 256
static constexpr int STAGE_BYTES = STAGE_ROWS * ROW_BYTES;  // 36864
static constexpr int STAGES = 3;
static constexpr int GEMM_SMEM = STAGES * STAGE_BYTES;      // 110592  -> 2 CTAs/SM
static constexpr int GTHREADS = 256;       // 8 warps: 2 over M x 4 over N (64x32 tiles)

// -------- scratch (static __device__; no allocation allowed) --------
__device__ __half g_xs [(size_t)T_TOK * C_DIM];
__device__ __half g_ys [(size_t)T_TOK * C_DIM];
__device__ __half g_aos[(size_t)T_TOK * C_DIM];
__device__ __half g_wq [(size_t)C_DIM * C_DIM];
__device__ __half g_wkv[(size_t)(2 * C_DIM) * C_DIM];
__device__ __half g_wo [(size_t)C_DIM * C_DIM];
__device__ float g_q  [(size_t)T_TOK * C_DIM];
__device__ float g_kv [(size_t)T_TOK * 2 * C_DIM];
__device__ float g_bkv[2 * C_DIM];

// -------- PTX helpers (sm_80+ only; no 'a'-suffix features) --------
__device__ __forceinline__ uint32_t smem_u32(const void* p) {
    uint32_t a;
    asm("{ .reg .u64 t; cvta.to.shared.u64 t, %1; cvt.u32.u64 %0, t; }" : "=r"(a) : "l"(p));
    return a;
}
#define CP_ASYNC16(s, g) \
    asm volatile("cp.async.cg.shared.global [%0], [%1], 16;" :: "r"((uint32_t)(s)), "l"(g) : "memory")
#define CP_COMMIT() asm volatile("cp.async.commit_group;" ::: "memory")

#define LDSM4(r, addr) \
    asm volatile("ldmatrix.sync.aligned.m8n8.x4.shared.b16 {%0,%1,%2,%3}, [%4];" \
        : "=r"((r)[0]), "=r"((r)[1]), "=r"((r)[2]), "=r"((r)[3]) : "r"(addr))

#define MMA16816(d, a, b0, b1) \
    asm volatile("mma.sync.aligned.m16n8k16.row.col.f32.f16.f16.f32 " \
        "{%0,%1,%2,%3}, {%4,%5,%6,%7}, {%8,%9}, {%0,%1,%2,%3};" \
        : "+f"((d)[0]), "+f"((d)[1]), "+f"((d)[2]), "+f"((d)[3]) \
        : "r"((a)[0]), "r"((a)[1]), "r"((a)[2]), "r"((a)[3]), "r"(b0), "r"(b1))

__device__ __forceinline__ uint32_t pack_h2(float x, float y) {
    __half2 h = __floats2half2_rn(x, y);
    return *(uint32_t*)&h;
}

// -------- fp32 -> fp16 conversions (vectorized) --------
__global__ void convert_acts_kernel(const float* __restrict__ x, const float* __restrict__ y,
                                    __half* __restrict__ xs, __half* __restrict__ ys) {
    const float* src = blockIdx.y ? y : x;
    __half* dst = blockIdx.y ? ys : xs;
    size_t i = ((size_t)blockIdx.x * blockDim.x + threadIdx.x) * 4;
    float4 v = *(const float4*)(src + i);
    uint2 o;
    o.x = pack_h2(v.x, v.y);
    o.y = pack_h2(v.z, v.w);
    *(uint2*)(dst + i) = o;
}
__global__ void convert_wgts_kernel(const float* __restrict__ Wq, const float* __restrict__ Wk,
                                    const float* __restrict__ Wv, const float* __restrict__ Wo,
                                    __half* __restrict__ wq, __half* __restrict__ wkv,
                                    __half* __restrict__ wo) {
    int sel = blockIdx.y;
    const float* src = (sel == 0) ? Wq : (sel == 1) ? Wk : (sel == 2) ? Wv : Wo;
    __half* dst = (sel == 0) ? wq : (sel == 1) ? wkv
                : (sel == 2) ? wkv + (size_t)C_DIM * C_DIM : wo;
    size_t i = ((size_t)blockIdx.x * blockDim.x + threadIdx.x) * 4;
    float4 v = *(const float4*)(src + i);
    uint2 o;
    o.x = pack_h2(v.x, v.y);
    o.y = pack_h2(v.z, v.w);
    *(uint2*)(dst + i) = o;
}
__global__ void concat_bias_kernel(const float* __restrict__ bk,
                                   const float* __restrict__ bv,
                                   float* __restrict__ dst) {
    int i = blockIdx.x * blockDim.x + threadIdx.x;
    dst[i] = (i < C_DIM) ? bk[i] : bv[i - C_DIM];
}

// -------- HMMA GEMM core (256 threads, 2 CTAs/SM): C = A@B^T + bias (+res) --------
// stage = 256 rows x 8 x 16B chunks = 2048 chunks / 256 threads = 8 iters
// parts 0..3 (one per ks step), 2 iters each.
__device__ __forceinline__ void load_tiles_part(const __half* __restrict__ A,
                                                const __half* __restrict__ B,
                                                int rowA0, int rowB0, int k0,
                                                uint32_t sbase, int tid, int part) {
#pragma unroll
    for (int i = 2 * part; i < 2 * part + 2; i++) {
        int idx = i * GTHREADS + tid;
        int row = idx >> 3;
        int c = idx & 7;
        const __half* g = (row < AROWS)
            ? A + (size_t)(rowA0 + row) * KDIM + (k0 + c * 8)
            : B + (size_t)(rowB0 + row - AROWS) * KDIM + (k0 + c * 8);
        CP_ASYNC16(sbase + row * ROW_BYTES + c * 16, g);
    }
}
__device__ __forceinline__ void load_tiles(const __half* __restrict__ A,
                                           const __half* __restrict__ B,
                                           int rowA0, int rowB0, int k0,
                                           uint32_t sbase, int tid) {
#pragma unroll
    for (int p = 0; p < 4; p++)
        load_tiles_part(A, B, rowA0, rowB0, k0, sbase, tid, p);
}

__device__ __forceinline__ void gemm_core(const __half* __restrict__ A,
                                          const __half* __restrict__ B,
                                          const float* __restrict__ bias,
                                          const float* __restrict__ residual,
                                          float* __restrict__ Cout, int ldc,
                                          int rowA0, int rowB0, char* smem) {
    uint32_t sb = smem_u32(smem);
    int tid = threadIdx.x;
    int wid = tid >> 5, lid = tid & 31;
    int warp_m = wid & 1;                   // 2 warps over M (64 rows each)
    int warp_n = wid >> 1;                  // 4 warps over N (32 cols each)

    float acc[4][4][4];
#pragma unroll
    for (int mi = 0; mi < 4; mi++)
#pragma unroll
        for (int ni = 0; ni < 4; ni++)
#pragma unroll
            for (int e = 0; e < 4; e++) acc[mi][ni][e] = 0.f;

#pragma unroll
    for (int s = 0; s < STAGES - 1; s++) {
        load_tiles(A, B, rowA0, rowB0, s * BK, sb + s * STAGE_BYTES, tid);
        CP_COMMIT();
    }

    uint32_t a_base = sb + (warp_m * 64 + (lid & 15)) * ROW_BYTES + ((lid >> 4) << 4);
    int g = lid >> 3;
    uint32_t b_base = sb + (AROWS + warp_n * 32 + ((g >> 1) << 3) + (lid & 7)) * ROW_BYTES
                         + ((g & 1) << 4);

    for (int k = 0; k < NKCH; k++) {
        int rem = NKCH - 1 - k;
        if (rem > STAGES - 2) rem = STAGES - 2;
        if (rem == 0) asm volatile("cp.async.wait_group 0;" ::: "memory");
        else         asm volatile("cp.async.wait_group 1;" ::: "memory");
        __syncthreads();

        uint32_t sa  = a_base + (k % STAGES) * STAGE_BYTES;
        uint32_t sbb = b_base + (k % STAGES) * STAGE_BYTES;

        int pk = k + STAGES - 1;
        bool do_pf = (pk < NKCH);
        uint32_t pf_base = sb + (pk % STAGES) * STAGE_BYTES;
        int pf_k0 = pk * BK;

#pragma unroll
        for (int ks = 0; ks < 4; ks++) {    // 4 x k16 per BK=64
            uint32_t afr[4][4], bfr[2][4];
#pragma unroll
            for (int mi = 0; mi < 4; mi++)
                LDSM4(afr[mi], sa + mi * 16 * ROW_BYTES + ks * 32);
#pragma unroll
            for (int ni2 = 0; ni2 < 2; ni2++)
                LDSM4(bfr[ni2], sbb + ni2 * 16 * ROW_BYTES + ks * 32);
            // spread prefetch across ks steps
            if (do_pf) {
                load_tiles_part(A, B, rowA0, rowB0, pf_k0, pf_base, tid, ks);
                if (ks == 3) CP_COMMIT();
            }
#pragma unroll
            for (int mi = 0; mi < 4; mi++)
#pragma unroll
                for (int ni2 = 0; ni2 < 2; ni2++) {
                    MMA16816(acc[mi][2 * ni2],     afr[mi], bfr[ni2][0], bfr[ni2][1]);
                    MMA16816(acc[mi][2 * ni2 + 1], afr[mi], bfr[ni2][2], bfr[ni2][3]);
                }
        }
    }

    int qrow = lid >> 2, qcol = (lid & 3) * 2;
#pragma unroll
    for (int mi = 0; mi < 4; mi++) {
#pragma unroll
        for (int ni = 0; ni < 4; ni++) {
            int r0 = rowA0 + warp_m * 64 + mi * 16 + qrow;
            int col = rowB0 + warp_n * 32 + ni * 8 + qcol;
            float2 bb = *(const float2*)(bias + col);
            float2 v0 = make_float2(acc[mi][ni][0] + bb.x, acc[mi][ni][1] + bb.y);
            float2 v1 = make_float2(acc[mi][ni][2] + bb.x, acc[mi][ni][3] + bb.y);
            if (residual) {
                float2 r0v = *(const float2*)(residual + (size_t)r0 * ldc + col);
                float2 r1v = *(const float2*)(residual + (size_t)(r0 + 8) * ldc + col);
                v0.x += r0v.x; v0.y += r0v.y;
                v1.x += r1v.x; v1.y += r1v.y;
            }
            *(float2*)(Cout + (size_t)r0 * ldc + col) = v0;
            *(float2*)(Cout + (size_t)(r0 + 8) * ldc + col) = v1;
        }
    }
}

// fused Q + KV GEMM: bx < 16 -> Q tile; bx >= 16 -> KV tile
__global__ void __launch_bounds__(GTHREADS, 2)
gemm_qkv_kernel(const __half* __restrict__ xs, const __half* __restrict__ ys,
                const __half* __restrict__ wq, const __half* __restrict__ wkv,
                const float* __restrict__ bq, const float* __restrict__ bkv,
                float* __restrict__ q, float* __restrict__ kv) {
    extern __shared__ __align__(16) char smem[];
    int bx = blockIdx.x;
    if (bx < 16) {
        gemm_core(xs, wq, bq, nullptr, q, C_DIM, blockIdx.y * BM, bx * BN, smem);
    } else {
        gemm_core(ys, wkv, bkv, nullptr, kv, 2 * C_DIM, blockIdx.y * BM, (bx - 16) * BN, smem);
    }
}

__global__ void __launch_bounds__(GTHREADS, 2)
gemm_kernel(const __half* __restrict__ A, const __half* __restrict__ B,
            const float* __restrict__ bias, const float* __restrict__ residual,
            float* __restrict__ Cout, int ldc) {
    extern __shared__ __align__(16) char smem[];
    gemm_core(A, B, bias, residual, Cout, ldc, blockIdx.y * BM, blockIdx.x * BN, smem);
}

// -------- per-token [8x8] head-mixing attention; writes fp16 directly --------
__global__ void __launch_bounds__(256)
attention_kernel(const float* __restrict__ Q, const float* __restrict__ KV,
                 __half* __restrict__ AOS) {
    int lid = threadIdx.x & 31;
    int t = blockIdx.x * 8 + (threadIdx.x >> 5);
    const float4* q  = (const float4*)(Q  + (size_t)t * C_DIM);
    const float4* kv = (const float4*)(KV + (size_t)t * 2 * C_DIM);
    const float scale = 0.0625f;  // 256^-0.5

    for (int h = 0; h < 8; h++) {
        float4 q0 = q[h * 64 + lid * 2];
        float4 q1 = q[h * 64 + lid * 2 + 1];
        float s[8];
#pragma unroll
        for (int gg = 0; gg < 8; gg++) {
            float4 k0 = kv[gg * 64 + lid * 2];
            float4 k1 = kv[gg * 64 + lid * 2 + 1];
            float d = q0.x * k0.x + q0.y * k0.y + q0.z * k0.z + q0.w * k0.w
                    + q1.x * k1.x + q1.y * k1.y + q1.z * k1.z + q1.w * k1.w;
#pragma unroll
            for (int off = 16; off >= 1; off >>= 1)
                d += __shfl_xor_sync(0xffffffffu, d, off);
            s[gg] = d * scale;
        }
        float m = s[0];
#pragma unroll
        for (int gg = 1; gg < 8; gg++) m = fmaxf(m, s[gg]);
        float e[8], sum = 0.f;
#pragma unroll
        for (int gg = 0; gg < 8; gg++) { e[gg] = __expf(s[gg] - m); sum += e[gg]; }
        float inv = 1.f / sum;
        float f[8];
#pragma unroll
        for (int j = 0; j < 8; j++) f[j] = 0.f;
#pragma unroll
        for (int gg = 0; gg < 8; gg++) {
            float p = e[gg] * inv;
            float4 v0 = kv[512 + gg * 64 + lid * 2];
            float4 v1 = kv[512 + gg * 64 + lid * 2 + 1];
            f[0] += p * v0.x; f[1] += p * v0.y; f[2] += p * v0.z; f[3] += p * v0.w;
            f[4] += p * v1.x; f[5] += p * v1.y; f[6] += p * v1.z; f[7] += p * v1.w;
        }
        uint4 H;
        H.x = pack_h2(f[0], f[1]); H.y = pack_h2(f[2], f[3]);
        H.z = pack_h2(f[4], f[5]); H.w = pack_h2(f[6], f[7]);
        size_t base = (size_t)t * C_DIM + h * 256 + lid * 8;
        *(uint4*)(AOS + base) = H;
    }
}

// -------- launch --------
extern "C" void kernel_launch(void* const* d_in, const int* in_sizes, int n_in,
                              void* d_out, int out_size) {
    (void)in_sizes; (void)n_in; (void)out_size;
    const float* x  = (const float*)d_in[0];
    const float* y  = (const float*)d_in[1];
    const float* Wq = (const float*)d_in[2];
    const float* bq = (const float*)d_in[3];
    const float* Wk = (const float*)d_in[4];
    const float* bk = (const float*)d_in[5];
    const float* Wv = (const float*)d_in[6];
    const float* bv = (const float*)d_in[7];
    const float* Wo = (const float*)d_in[8];
    const float* bo = (const float*)d_in[9];
    float* out = (float*)d_out;

    cudaFuncSetAttribute(gemm_kernel, cudaFuncAttributeMaxDynamicSharedMemorySize, GEMM_SMEM);
    cudaFuncSetAttribute(gemm_qkv_kernel, cudaFuncAttributeMaxDynamicSharedMemorySize, GEMM_SMEM);

    __half *xs, *ys, *aos, *wq, *wkv, *wo;
    float *q, *kv, *bkv;
    cudaGetSymbolAddress((void**)&xs,  g_xs);
    cudaGetSymbolAddress((void**)&ys,  g_ys);
    cudaGetSymbolAddress((void**)&aos, g_aos);
    cudaGetSymbolAddress((void**)&wq,  g_wq);
    cudaGetSymbolAddress((void**)&wkv, g_wkv);
    cudaGetSymbolAddress((void**)&wo,  g_wo);
    cudaGetSymbolAddress((void**)&q,   g_q);
    cudaGetSymbolAddress((void**)&kv,  g_kv);
    cudaGetSymbolAddress((void**)&bkv, g_bkv);

    const int actBlocks = (T_TOK * C_DIM) / (256 * 4);   // 8192 per tensor
    const int wgtBlocks = (C_DIM * C_DIM) / (256 * 4);   // 4096 per tensor

    // launch order chosen so ncu (-s 5) profiles the O GEMM (index 5)
    concat_bias_kernel<<<16, 256>>>(bk, bv, bkv);                            // 0
    convert_acts_kernel<<<dim3(actBlocks, 2), 256>>>(x, y, xs, ys);          // 1
    convert_wgts_kernel<<<dim3(wgtBlocks, 4), 256>>>(Wq, Wk, Wv, Wo,
                                                     wq, wkv, wo);           // 2
    gemm_qkv_kernel<<<dim3(48, 64), GTHREADS, GEMM_SMEM>>>(xs, ys, wq, wkv,
                                                           bq, bkv, q, kv);  // 3
    attention_kernel<<<T_TOK / 8, 256>>>(q, kv, aos);                        // 4
    gemm_kernel<<<dim3(16, 64), GTHREADS, GEMM_SMEM>>>(aos, wo, bo, x, out,
                                                       C_DIM);               // 5
}